// round 5
// baseline (speedup 1.0000x reference)
#include <cuda_runtime.h>

// Deriv2Matern52: out[i,a,j,b] = c^2 * ( (a==b)*A(i,j)*inv_l2[a] - 5*fr(i,j)*D[i,j,a]*D[i,j,b] )
//
// One thread per (i,j) pair; for each a the thread writes the full 8-float
// b-row with a single 256-bit store (st.global.cs.v8.f32, sm_100+ PTX 8.7).
// Lane t writes 32B at base+32*t -> each warp store instruction covers 1024B
// fully contiguous. Store instruction count per byte halves vs STG.128.

#define D_DIM 8
#define JT 256          // j-tile per block = threads per block
#define SQRT5F 2.2360679774997896f

__device__ __forceinline__ void stg256_cs(float* p,
    float o0, float o1, float o2, float o3,
    float o4, float o5, float o6, float o7)
{
    asm volatile(
        "st.global.cs.v8.f32 [%0], {%1,%2,%3,%4,%5,%6,%7,%8};"
        :: "l"(p),
           "f"(o0), "f"(o1), "f"(o2), "f"(o3),
           "f"(o4), "f"(o5), "f"(o6), "f"(o7)
        : "memory");
}

__global__ __launch_bounds__(JT) void deriv2_matern52_kernel(
    const float* __restrict__ X1,   // [n, 8]
    const float* __restrict__ X2,   // [m, 8]
    const float* __restrict__ cptr, // [1]
    const float* __restrict__ lptr, // [8]
    float* __restrict__ out,        // [n, 8, m, 8]
    int m)
{
    const int t = threadIdx.x;
    const int i = blockIdx.y;
    const int j = blockIdx.x * JT + t;

    // lengthscales -> inv_l2 (uniform, L1-resident)
    float invl2[D_DIM];
#pragma unroll
    for (int a = 0; a < D_DIM; a++) {
        float lv = __ldg(lptr + a);
        invl2[a] = 1.0f / (lv * lv);
    }
    float cv = __ldg(cptr);
    float c2 = cv * cv;

    const float4* x1p = reinterpret_cast<const float4*>(X1 + (size_t)i * D_DIM);
    const float4* x2p = reinterpret_cast<const float4*>(X2 + (size_t)j * D_DIM);
    float4 x1a = __ldg(x1p);
    float4 x1b = __ldg(x1p + 1);
    float4 x2a = __ldg(x2p);
    float4 x2b = __ldg(x2p + 1);

    float dx[D_DIM];
    dx[0] = x1a.x - x2a.x; dx[1] = x1a.y - x2a.y;
    dx[2] = x1a.z - x2a.z; dx[3] = x1a.w - x2a.w;
    dx[4] = x1b.x - x2b.x; dx[5] = x1b.y - x2b.y;
    dx[6] = x1b.z - x2b.z; dx[7] = x1b.w - x2b.w;

    float s = 0.0f;
    float Dv[D_DIM];
#pragma unroll
    for (int a = 0; a < D_DIM; a++) {
        Dv[a] = dx[a] * invl2[a];
        s = fmaf(dx[a], Dv[a], s);
    }
    float r   = sqrtf(s);
    float fr  = (5.0f / 3.0f) * __expf(-SQRT5F * r);
    float A   = fr * fmaf(SQRT5F, r, 1.0f);
    float Ac2 = A * c2;
    float m5  = -5.0f * fr * c2;

    float Ad[D_DIM];
#pragma unroll
    for (int a = 0; a < D_DIM; a++)
        Ad[a] = Ac2 * invl2[a];

    // base element index of (i, a=0, j, b=0); each a-row is 32B-aligned
    float* dst = out + (((size_t)i * D_DIM) * (size_t)m + (size_t)j) * D_DIM;
    const size_t astride = (size_t)m * D_DIM;

#pragma unroll
    for (int a = 0; a < D_DIM; a++) {
        float ta = m5 * Dv[a];
        float o0 = ta * Dv[0];
        float o1 = ta * Dv[1];
        float o2 = ta * Dv[2];
        float o3 = ta * Dv[3];
        float o4 = ta * Dv[4];
        float o5 = ta * Dv[5];
        float o6 = ta * Dv[6];
        float o7 = ta * Dv[7];
        switch (a) {
            case 0: o0 += Ad[0]; break;
            case 1: o1 += Ad[1]; break;
            case 2: o2 += Ad[2]; break;
            case 3: o3 += Ad[3]; break;
            case 4: o4 += Ad[4]; break;
            case 5: o5 += Ad[5]; break;
            case 6: o6 += Ad[6]; break;
            case 7: o7 += Ad[7]; break;
        }
        stg256_cs(dst + (size_t)a * astride, o0, o1, o2, o3, o4, o5, o6, o7);
    }
}

extern "C" void kernel_launch(void* const* d_in, const int* in_sizes, int n_in,
                              void* d_out, int out_size)
{
    const float* X1 = (const float*)d_in[0];
    const float* X2 = (const float*)d_in[1];
    const float* c  = (const float*)d_in[2];
    const float* l  = (const float*)d_in[3];
    float* out = (float*)d_out;

    int n = in_sizes[0] / D_DIM;
    int m = in_sizes[1] / D_DIM;

    dim3 grid(m / JT, n);
    deriv2_matern52_kernel<<<grid, JT>>>(X1, X2, c, l, out, m);
}